// round 1
// baseline (speedup 1.0000x reference)
#include <cuda_runtime.h>
#include <math.h>

#define NG        1536
#define WID       160
#define HEI       128
#define FX_       146.44f
#define FY_       146.44f
#define CX_       80.0f
#define CY_       64.0f
#define EPS2D_    0.3f
#define NEAR_     0.01f
#define FAR_      1e10f
#define NSEG      8
#define SEGLEN    (NG / NSEG)          // 192
#define LOG2E_    1.4426950408889634f
#define SKIP_THR  (-25.0f)

// ---------------- device scratch (no allocation allowed) ----------------
__device__ float4 g_pre[NG * 3];       // unsorted packed: [u,v,A2,B2],[C2,lo,r,g],[b,-,-,-]
__device__ float  g_keys[NG];          // depth sort keys (inf if masked)
__device__ float4 g_sorted[NG * 2];    // sorted: 2 float4 per gaussian
__device__ float  g_sb[NG];            // sorted blue channel

__device__ __forceinline__ float fast_exp2(float x) {
    float r;
    asm("ex2.approx.f32 %0, %1;" : "=f"(r) : "f"(x));
    return r;
}

// ---------------- kernel 1: per-gaussian preprocess ----------------
__global__ void preprocess_kernel(const float* __restrict__ means,
                                  const float* __restrict__ quats,
                                  const float* __restrict__ log_scales,
                                  const float* __restrict__ opacity_logits,
                                  const float* __restrict__ sh,
                                  const float* __restrict__ c2w) {
    int n = blockIdx.x * blockDim.x + threadIdx.x;
    if (n >= NG) return;

    // camera: R = c2w[:, :3,:3] * diag-ish column scale (1,-1,-1); W = R^T (w2c rotation)
    const float sgn[3] = {1.f, -1.f, -1.f};
    float Wm[3][3];
#pragma unroll
    for (int i = 0; i < 3; ++i)
#pragma unroll
        for (int j = 0; j < 3; ++j)
            Wm[i][j] = c2w[j * 4 + i] * sgn[i];   // W[i][j] = R[j][i] = c2w[j][i]*s[i]

    float tx0 = c2w[3], ty0 = c2w[7], tz0 = c2w[11];
    float tw[3];
#pragma unroll
    for (int i = 0; i < 3; ++i)
        tw[i] = -(Wm[i][0] * tx0 + Wm[i][1] * ty0 + Wm[i][2] * tz0);

    float mx = means[3 * n + 0], my = means[3 * n + 1], mz = means[3 * n + 2];

    float mc[3];
#pragma unroll
    for (int i = 0; i < 3; ++i)
        mc[i] = Wm[i][0] * mx + Wm[i][1] * my + Wm[i][2] * mz + tw[i];
    float depth = mc[2];
    bool mask = (depth > NEAR_) && (depth < FAR_);

    // view direction from camera position (c2w translation)
    float dx = mx - tx0, dy = my - ty0, dz = mz - tz0;
    float rn = rsqrtf(dx * dx + dy * dy + dz * dz);
    float x = dx * rn, y = dy * rn, z = dz * rn;

    // SH basis (degree 3, 16 coeffs)
    float basis[16];
    basis[0]  = 0.282095f;
    basis[1]  = -0.488603f * y;
    basis[2]  = 0.488603f * z;
    basis[3]  = -0.488603f * x;
    basis[4]  = 1.092548f * x * y;
    basis[5]  = -1.092548f * y * z;
    basis[6]  = 0.315392f * (3.f * z * z - 1.f);
    basis[7]  = -1.092548f * x * z;
    basis[8]  = 0.546274f * (x * x - y * y);
    basis[9]  = -0.590044f * y * (3.f * x * x - y * y);
    basis[10] = 2.890611f * x * y * z;
    basis[11] = -0.457046f * y * (5.f * z * z - 1.f);
    basis[12] = 0.373176f * z * (5.f * z * z - 3.f);
    basis[13] = -0.457046f * x * (5.f * z * z - 1.f);
    basis[14] = 1.445306f * z * (x * x - y * y);
    basis[15] = -0.590044f * x * (x * x - 3.f * y * y);

    float col[3] = {0.f, 0.f, 0.f};
    const float* shn = sh + n * 48;
#pragma unroll
    for (int k = 0; k < 16; ++k) {
        col[0] = fmaf(basis[k], shn[k * 3 + 0], col[0]);
        col[1] = fmaf(basis[k], shn[k * 3 + 1], col[1]);
        col[2] = fmaf(basis[k], shn[k * 3 + 2], col[2]);
    }
#pragma unroll
    for (int c = 0; c < 3; ++c) col[c] = fmaxf(col[c] + 0.5f, 0.f);

    // quaternion -> rotation (w,x,y,z order)
    float qw = quats[4 * n + 0], qx = quats[4 * n + 1], qy = quats[4 * n + 2], qz = quats[4 * n + 3];
    float qn = rsqrtf(qw * qw + qx * qx + qy * qy + qz * qz);
    qw *= qn; qx *= qn; qy *= qn; qz *= qn;
    float Rg[3][3];
    Rg[0][0] = 1.f - 2.f * (qy * qy + qz * qz);
    Rg[0][1] = 2.f * (qx * qy - qz * qw);
    Rg[0][2] = 2.f * (qx * qz + qy * qw);
    Rg[1][0] = 2.f * (qx * qy + qz * qw);
    Rg[1][1] = 1.f - 2.f * (qx * qx + qz * qz);
    Rg[1][2] = 2.f * (qy * qz - qx * qw);
    Rg[2][0] = 2.f * (qx * qz - qy * qw);
    Rg[2][1] = 2.f * (qy * qz + qx * qw);
    Rg[2][2] = 1.f - 2.f * (qx * qx + qy * qy);

    float e0 = expf(log_scales[3 * n + 0]);
    float e1 = expf(log_scales[3 * n + 1]);
    float e2 = expf(log_scales[3 * n + 2]);

    // M = Rg * scale (columns); Mc = W @ M; cov_cam = Mc Mc^T
    float Mc[3][3];
#pragma unroll
    for (int i = 0; i < 3; ++i) {
        float m0 = Wm[i][0] * Rg[0][0] + Wm[i][1] * Rg[1][0] + Wm[i][2] * Rg[2][0];
        float m1 = Wm[i][0] * Rg[0][1] + Wm[i][1] * Rg[1][1] + Wm[i][2] * Rg[2][1];
        float m2 = Wm[i][0] * Rg[0][2] + Wm[i][1] * Rg[1][2] + Wm[i][2] * Rg[2][2];
        Mc[i][0] = m0 * e0; Mc[i][1] = m1 * e1; Mc[i][2] = m2 * e2;
    }

    float tcx = mc[0], tcy = mc[1], tcz = mc[2];
    float rz = 1.f / tcz;
    float j00 = FX_ * rz, j02 = -FX_ * tcx * rz * rz;
    float j11 = FY_ * rz, j12 = -FY_ * tcy * rz * rz;

    // P = J @ Mc (2x3); cov2d = P P^T
    float P0[3], P1[3];
#pragma unroll
    for (int j = 0; j < 3; ++j) {
        P0[j] = j00 * Mc[0][j] + j02 * Mc[2][j];
        P1[j] = j11 * Mc[1][j] + j12 * Mc[2][j];
    }
    float a = P0[0] * P0[0] + P0[1] * P0[1] + P0[2] * P0[2] + EPS2D_;
    float cc = P1[0] * P1[0] + P1[1] * P1[1] + P1[2] * P1[2] + EPS2D_;
    float b = P0[0] * P1[0] + P0[1] * P1[1] + P0[2] * P1[2];
    float det = a * cc - b * b;
    float inv = 1.f / det;
    float A = cc * inv, B = -b * inv, C = a * inv;

    float A2 = -0.5f * LOG2E_ * A;
    float C2 = -0.5f * LOG2E_ * C;
    float B2 = -LOG2E_ * B;

    float u = FX_ * tcx * rz + CX_;
    float v = FY_ * tcy * rz + CY_;

    float opac = 1.f / (1.f + expf(-opacity_logits[n]));
    float lo = log2f(opac);
    if (!mask) lo = -1e30f;

    g_pre[3 * n + 0] = make_float4(u, v, A2, B2);
    g_pre[3 * n + 1] = make_float4(C2, lo, col[0], col[1]);
    g_pre[3 * n + 2] = make_float4(col[2], 0.f, 0.f, 0.f);
    g_keys[n] = mask ? depth : __int_as_float(0x7f800000);
}

// ---------------- kernel 2: single-block bitonic sort + gather ----------------
__global__ void sort_gather_kernel() {
    __shared__ float sk[2048];
    __shared__ int   sv[2048];
    int t = threadIdx.x;
    for (int i = t; i < 2048; i += 1024) {
        sk[i] = (i < NG) ? g_keys[i] : __int_as_float(0x7f800000);
        sv[i] = i;
    }
    __syncthreads();

    for (int k = 2; k <= 2048; k <<= 1) {
        for (int j = k >> 1; j > 0; j >>= 1) {
            for (int i = t; i < 2048; i += 1024) {
                int ixj = i ^ j;
                if (ixj > i) {
                    bool up = ((i & k) == 0);   // ascending
                    float a = sk[i], b = sk[ixj];
                    if ((a > b) == up) {
                        sk[i] = b; sk[ixj] = a;
                        int va = sv[i]; sv[i] = sv[ixj]; sv[ixj] = va;
                    }
                }
            }
            __syncthreads();
        }
    }

    for (int i = t; i < NG; i += 1024) {
        int s = sv[i];
        g_sorted[2 * i + 0] = g_pre[3 * s + 0];
        g_sorted[2 * i + 1] = g_pre[3 * s + 1];
        g_sb[i]             = g_pre[3 * s + 2].x;
    }
}

// ---------------- kernel 3: segmented per-pixel compositing ----------------
__global__ void __launch_bounds__(256) render_kernel(float* __restrict__ out) {
    int lane = threadIdx.x;              // 0..31  -> pixel within group
    int seg  = threadIdx.y;              // 0..7   -> gaussian segment
    int pix  = blockIdx.x * 32 + lane;   // 0..20479
    int px = pix % WID;
    int py = pix / WID;
    float fx = (float)px, fy = (float)py;

    float T = 1.f, cr = 0.f, cg = 0.f, cb = 0.f;
    int i0 = seg * SEGLEN;
    const float4* __restrict__ gp = g_sorted;

    for (int i = i0; i < i0 + SEGLEN; ++i) {
        float4 a  = __ldg(&gp[2 * i + 0]);     // u, v, A2, B2
        float4 b4 = __ldg(&gp[2 * i + 1]);     // C2, lo, r, g
        float dx = fx - a.x;
        float dy = fy - a.y;
        float p = fmaf(a.z * dx, dx, b4.y);    // A2*dx^2 + lo
        p = fmaf(b4.x * dy, dy, p);            // + C2*dy^2
        p = fmaf(a.w * dx, dy, p);             // + B2*dx*dy
        if (p > SKIP_THR) {
            float alpha = fminf(fast_exp2(p), 0.999f);
            float w = T * alpha;
            cr = fmaf(w, b4.z, cr);
            cg = fmaf(w, b4.w, cg);
            cb = fmaf(w, __ldg(&g_sb[i]), cb);
            T = fmaf(-T, alpha, T);            // T *= (1 - alpha)
        }
    }

    __shared__ float4 sred[NSEG][32];
    sred[seg][lane] = make_float4(T, cr, cg, cb);
    __syncthreads();

    if (seg == 0) {
        float Tp = 1.f, R = 0.f, G = 0.f, B = 0.f;
#pragma unroll
        for (int k = 0; k < NSEG; ++k) {
            float4 vv = sred[k][lane];
            R = fmaf(Tp, vv.y, R);
            G = fmaf(Tp, vv.z, G);
            B = fmaf(Tp, vv.w, B);
            Tp *= vv.x;
        }
        out[pix * 3 + 0] = R;
        out[pix * 3 + 1] = G;
        out[pix * 3 + 2] = B;
    }
}

// ---------------- launch ----------------
extern "C" void kernel_launch(void* const* d_in, const int* in_sizes, int n_in,
                              void* d_out, int out_size) {
    const float* means   = (const float*)d_in[0];
    const float* quats   = (const float*)d_in[1];
    const float* lscales = (const float*)d_in[2];
    const float* opl     = (const float*)d_in[3];
    const float* sh      = (const float*)d_in[4];
    const float* c2w     = (const float*)d_in[5];
    float* out = (float*)d_out;

    preprocess_kernel<<<(NG + 255) / 256, 256>>>(means, quats, lscales, opl, sh, c2w);
    sort_gather_kernel<<<1, 1024>>>();
    render_kernel<<<(WID * HEI) / 32, dim3(32, NSEG)>>>(out);
}

// round 2
// speedup vs baseline: 1.3345x; 1.3345x over previous
#include <cuda_runtime.h>
#include <math.h>

#define NG        1536
#define WID       160
#define HEI       128
#define FX_       146.44f
#define FY_       146.44f
#define CX_       80.0f
#define CY_       64.0f
#define EPS2D_    0.3f
#define NEAR_     0.01f
#define FAR_      1e10f
#define NSEG      8
#define SEGLEN    (NG / NSEG)          // 192
#define LOG2E_    1.4426950408889634f
#define SKIP_THR  (-25.0f)             // in log2 units

// ---------------- device scratch (no allocation allowed) ----------------
__device__ float4 g_pre0[NG];          // u, v, axx, axy   (log2-space conic, opacity folded)
__device__ float4 g_pre1[NG];          // ayy, lo, r, g
__device__ float  g_preb[NG];          // blue
__device__ float4 g_prec[NG];          // u, v, rx, ry     (cull bbox)
__device__ float  g_keys[NG];          // depth sort keys (inf if masked)

__device__ float4 g_s0[NG];            // sorted coeffs 0
__device__ float4 g_s1[NG];            // sorted coeffs 1
__device__ float4 g_scul[NG];          // sorted cull bbox
__device__ float  g_sbl[NG];           // sorted blue

__device__ __forceinline__ float fast_exp2(float x) {
    float r;
    asm("ex2.approx.f32 %0, %1;" : "=f"(r) : "f"(x));
    return r;
}

// ---------------- kernel 1: per-gaussian preprocess ----------------
__global__ void preprocess_kernel(const float* __restrict__ means,
                                  const float* __restrict__ quats,
                                  const float* __restrict__ log_scales,
                                  const float* __restrict__ opacity_logits,
                                  const float* __restrict__ sh,
                                  const float* __restrict__ c2w) {
    int n = blockIdx.x * blockDim.x + threadIdx.x;
    if (n >= NG) return;

    const float sgn[3] = {1.f, -1.f, -1.f};
    float Wm[3][3];
#pragma unroll
    for (int i = 0; i < 3; ++i)
#pragma unroll
        for (int j = 0; j < 3; ++j)
            Wm[i][j] = c2w[j * 4 + i] * sgn[i];

    float tx0 = c2w[3], ty0 = c2w[7], tz0 = c2w[11];
    float tw[3];
#pragma unroll
    for (int i = 0; i < 3; ++i)
        tw[i] = -(Wm[i][0] * tx0 + Wm[i][1] * ty0 + Wm[i][2] * tz0);

    float mx = means[3 * n + 0], my = means[3 * n + 1], mz = means[3 * n + 2];

    float mc[3];
#pragma unroll
    for (int i = 0; i < 3; ++i)
        mc[i] = Wm[i][0] * mx + Wm[i][1] * my + Wm[i][2] * mz + tw[i];
    float depth = mc[2];
    bool mask = (depth > NEAR_) && (depth < FAR_);

    // view direction
    float dx = mx - tx0, dy = my - ty0, dz = mz - tz0;
    float rn = rsqrtf(dx * dx + dy * dy + dz * dz);
    float x = dx * rn, y = dy * rn, z = dz * rn;

    // SH basis (degree 3)
    float basis[16];
    basis[0]  = 0.282095f;
    basis[1]  = -0.488603f * y;
    basis[2]  = 0.488603f * z;
    basis[3]  = -0.488603f * x;
    basis[4]  = 1.092548f * x * y;
    basis[5]  = -1.092548f * y * z;
    basis[6]  = 0.315392f * (3.f * z * z - 1.f);
    basis[7]  = -1.092548f * x * z;
    basis[8]  = 0.546274f * (x * x - y * y);
    basis[9]  = -0.590044f * y * (3.f * x * x - y * y);
    basis[10] = 2.890611f * x * y * z;
    basis[11] = -0.457046f * y * (5.f * z * z - 1.f);
    basis[12] = 0.373176f * z * (5.f * z * z - 3.f);
    basis[13] = -0.457046f * x * (5.f * z * z - 1.f);
    basis[14] = 1.445306f * z * (x * x - y * y);
    basis[15] = -0.590044f * x * (x * x - 3.f * y * y);

    float col[3] = {0.f, 0.f, 0.f};
    const float* shn = sh + n * 48;
#pragma unroll
    for (int k = 0; k < 16; ++k) {
        col[0] = fmaf(basis[k], shn[k * 3 + 0], col[0]);
        col[1] = fmaf(basis[k], shn[k * 3 + 1], col[1]);
        col[2] = fmaf(basis[k], shn[k * 3 + 2], col[2]);
    }
#pragma unroll
    for (int c = 0; c < 3; ++c) col[c] = fmaxf(col[c] + 0.5f, 0.f);

    // quaternion -> rotation
    float qw = quats[4 * n + 0], qx = quats[4 * n + 1], qy = quats[4 * n + 2], qz = quats[4 * n + 3];
    float qn = rsqrtf(qw * qw + qx * qx + qy * qy + qz * qz);
    qw *= qn; qx *= qn; qy *= qn; qz *= qn;
    float Rg[3][3];
    Rg[0][0] = 1.f - 2.f * (qy * qy + qz * qz);
    Rg[0][1] = 2.f * (qx * qy - qz * qw);
    Rg[0][2] = 2.f * (qx * qz + qy * qw);
    Rg[1][0] = 2.f * (qx * qy + qz * qw);
    Rg[1][1] = 1.f - 2.f * (qx * qx + qz * qz);
    Rg[1][2] = 2.f * (qy * qz - qx * qw);
    Rg[2][0] = 2.f * (qx * qz - qy * qw);
    Rg[2][1] = 2.f * (qy * qz + qx * qw);
    Rg[2][2] = 1.f - 2.f * (qx * qx + qy * qy);

    float e0 = expf(log_scales[3 * n + 0]);
    float e1 = expf(log_scales[3 * n + 1]);
    float e2 = expf(log_scales[3 * n + 2]);

    float Mc[3][3];
#pragma unroll
    for (int i = 0; i < 3; ++i) {
        float m0 = Wm[i][0] * Rg[0][0] + Wm[i][1] * Rg[1][0] + Wm[i][2] * Rg[2][0];
        float m1 = Wm[i][0] * Rg[0][1] + Wm[i][1] * Rg[1][1] + Wm[i][2] * Rg[2][1];
        float m2 = Wm[i][0] * Rg[0][2] + Wm[i][1] * Rg[1][2] + Wm[i][2] * Rg[2][2];
        Mc[i][0] = m0 * e0; Mc[i][1] = m1 * e1; Mc[i][2] = m2 * e2;
    }

    float tcx = mc[0], tcy = mc[1], tcz = mc[2];
    float rz = 1.f / tcz;
    float j00 = FX_ * rz, j02 = -FX_ * tcx * rz * rz;
    float j11 = FY_ * rz, j12 = -FY_ * tcy * rz * rz;

    float P0[3], P1[3];
#pragma unroll
    for (int j = 0; j < 3; ++j) {
        P0[j] = j00 * Mc[0][j] + j02 * Mc[2][j];
        P1[j] = j11 * Mc[1][j] + j12 * Mc[2][j];
    }
    float a = P0[0] * P0[0] + P0[1] * P0[1] + P0[2] * P0[2] + EPS2D_;
    float cc = P1[0] * P1[0] + P1[1] * P1[1] + P1[2] * P1[2] + EPS2D_;
    float b = P0[0] * P1[0] + P0[1] * P1[1] + P0[2] * P1[2];
    float det = a * cc - b * b;
    float inv = 1.f / det;
    float A = cc * inv, B = -b * inv, C = a * inv;

    // log2-space conic: p(d) = axx dx^2 + axy dx dy + ayy dy^2 + lo
    float axx = -0.5f * LOG2E_ * A;
    float ayy = -0.5f * LOG2E_ * C;
    float axy = -LOG2E_ * B;

    float u = FX_ * tcx * rz + CX_;
    float v = FY_ * tcy * rz + CY_;

    float opac = 1.f / (1.f + expf(-opacity_logits[n]));
    float lo = log2f(opac);
    if (!mask) lo = -1e30f;

    // bbox of ellipse p = SKIP_THR (positive-definite form: aq dx^2 + bq dxdy + cq dy^2 = t)
    float aq = -axx, bq = -axy, cq = -ayy;
    float t = lo - SKIP_THR;               // > 0 when peak can exceed threshold
    float rx = -1.f, ry = -1.f;
    if (t > 0.f) {
        float denom = 4.f * aq * cq - bq * bq;   // > 0 (PD)
        float rden = 4.f * t / denom;
        rx = sqrtf(cq * rden) + 1.0f;
        ry = sqrtf(aq * rden) + 1.0f;
    }

    g_pre0[n] = make_float4(u, v, axx, axy);
    g_pre1[n] = make_float4(ayy, lo, col[0], col[1]);
    g_preb[n] = col[2];
    g_prec[n] = make_float4(u, v, rx, ry);
    g_keys[n] = mask ? depth : __int_as_float(0x7f800000);
}

// ---------------- kernel 2: single-block bitonic sort + gather ----------------
__global__ void sort_gather_kernel() {
    __shared__ float sk[2048];
    __shared__ int   sv[2048];
    int t = threadIdx.x;
    for (int i = t; i < 2048; i += 1024) {
        sk[i] = (i < NG) ? g_keys[i] : __int_as_float(0x7f800000);
        sv[i] = i;
    }
    __syncthreads();

    for (int k = 2; k <= 2048; k <<= 1) {
        for (int j = k >> 1; j > 0; j >>= 1) {
            for (int i = t; i < 2048; i += 1024) {
                int ixj = i ^ j;
                if (ixj > i) {
                    bool up = ((i & k) == 0);
                    float a = sk[i], b = sk[ixj];
                    if ((a > b) == up) {
                        sk[i] = b; sk[ixj] = a;
                        int va = sv[i]; sv[i] = sv[ixj]; sv[ixj] = va;
                    }
                }
            }
            __syncthreads();
        }
    }

    for (int i = t; i < NG; i += 1024) {
        int s = sv[i];
        g_s0[i]   = g_pre0[s];
        g_s1[i]   = g_pre1[s];
        g_scul[i] = g_prec[s];
        g_sbl[i]  = g_preb[s];
    }
}

// ---------------- kernel 3: culled, segmented per-pixel compositing ----------------
__global__ void __launch_bounds__(256) render_kernel(float* __restrict__ out) {
    int lane = threadIdx.x;              // 0..31  -> pixel within 32-px row strip
    int seg  = threadIdx.y;              // 0..7   -> gaussian segment
    int pixbase = blockIdx.x * 32;       // strip start (strips never cross rows: 160 = 5*32)
    int px0 = pixbase % WID;
    int py  = pixbase / WID;

    float yc = (float)py;
    float xc = (float)px0 + 15.5f;
    float lx = (float)lane - 15.5f;      // pixel x relative to strip center
    float fx0 = (float)px0;
    float fx1 = (float)(px0 + 31);

    __shared__ unsigned short slist[NSEG][SEGLEN];
    __shared__ float4 sred[NSEG][32];

    // ---- scan & compact this warp's segment ----
    int i0 = seg * SEGLEN;
    int cnt = 0;
#pragma unroll
    for (int r = 0; r < SEGLEN / 32; ++r) {
        int g = i0 + r * 32 + lane;
        float4 cb = g_scul[g];           // u, v, rx, ry (coalesced)
        bool pass = (fabsf(cb.y - yc) < cb.w) &&
                    (cb.x + cb.z > fx0) && (cb.x - cb.z < fx1);
        unsigned m = __ballot_sync(0xffffffffu, pass);
        if (pass)
            slist[seg][cnt + __popc(m & ((1u << lane) - 1u))] = (unsigned short)g;
        cnt += __popc(m);
    }
    __syncwarp();

    // ---- composite survivors (front-to-back within segment) ----
    float T = 1.f, cr = 0.f, cg = 0.f, cbl = 0.f;
    for (int j = 0; j < cnt; ++j) {
        int g = slist[seg][j];
        float4 a  = __ldg(&g_s0[g]);     // u, v, axx, axy  (broadcast)
        float4 b4 = __ldg(&g_s1[g]);     // ayy, lo, r, g
        float du = xc - a.x;             // uniform across warp
        float dv = yc - a.y;
        float tx = a.z * du;
        float s  = fmaf(a.w, dv, tx);            // axx*du + axy*dv
        float k0 = fmaf(du, s, b4.y);            // lo + du*(...)
        k0 = fmaf(b4.x * dv, dv, k0);            // + ayy*dv^2
        float k1 = fmaf(a.w, dv, tx + tx);       // 2*axx*du + axy*dv
        float p  = fmaf(fmaf(a.z, lx, k1), lx, k0);  // per-lane: 2 FMA
        if (p > SKIP_THR) {
            float alpha = fminf(fast_exp2(p), 0.999f);
            float w = T * alpha;
            cr  = fmaf(w, b4.z, cr);
            cg  = fmaf(w, b4.w, cg);
            cbl = fmaf(w, __ldg(&g_sbl[g]), cbl);
            T   = fmaf(-T, alpha, T);
        }
    }

    sred[seg][lane] = make_float4(T, cr, cg, cbl);
    __syncthreads();

    if (seg == 0) {
        float Tp = 1.f, R = 0.f, G = 0.f, B = 0.f;
#pragma unroll
        for (int k = 0; k < NSEG; ++k) {
            float4 vv = sred[k][lane];
            R = fmaf(Tp, vv.y, R);
            G = fmaf(Tp, vv.z, G);
            B = fmaf(Tp, vv.w, B);
            Tp *= vv.x;
        }
        int pix = pixbase + lane;
        out[pix * 3 + 0] = R;
        out[pix * 3 + 1] = G;
        out[pix * 3 + 2] = B;
    }
}

// ---------------- launch ----------------
extern "C" void kernel_launch(void* const* d_in, const int* in_sizes, int n_in,
                              void* d_out, int out_size) {
    const float* means   = (const float*)d_in[0];
    const float* quats   = (const float*)d_in[1];
    const float* lscales = (const float*)d_in[2];
    const float* opl     = (const float*)d_in[3];
    const float* sh      = (const float*)d_in[4];
    const float* c2w     = (const float*)d_in[5];
    float* out = (float*)d_out;

    preprocess_kernel<<<(NG + 255) / 256, 256>>>(means, quats, lscales, opl, sh, c2w);
    sort_gather_kernel<<<1, 1024>>>();
    render_kernel<<<(WID * HEI) / 32, dim3(32, NSEG)>>>(out);
}

// round 3
// speedup vs baseline: 1.7206x; 1.2893x over previous
#include <cuda_runtime.h>
#include <math.h>

#define NG        1536
#define WID       160
#define HEI       128
#define FX_       146.44f
#define FY_       146.44f
#define CX_       80.0f
#define CY_       64.0f
#define EPS2D_    0.3f
#define NEAR_     0.01f
#define FAR_      1e10f
#define NSEG      16
#define SEGLEN    (NG / NSEG)          // 96
#define LOG2E_    1.4426950408889634f
#define SKIP_THR  (-20.0f)             // log2 units; culled alpha <= ~1e-6
#define FINF      __int_as_float(0x7f800000)

// ---------------- device scratch (sorted-by-depth gaussian data) ----------------
__device__ float4 g_s0[NG];            // u, v, axx, axy   (log2-space conic, opacity folded)
__device__ float4 g_s1[NG];            // ayy, lo, r, g
__device__ float4 g_scul[NG];          // u, v, rx, ry     (cull bbox)
__device__ float  g_sbl[NG];           // blue

__device__ __forceinline__ float fast_exp2(float x) {
    float r;
    asm("ex2.approx.f32 %0, %1;" : "=f"(r) : "f"(x));
    return r;
}

// ---------------- kernel 1: preprocess + counting-rank scatter ----------------
__global__ void __launch_bounds__(256) pre_rank_kernel(const float* __restrict__ means,
                                                       const float* __restrict__ quats,
                                                       const float* __restrict__ log_scales,
                                                       const float* __restrict__ opacity_logits,
                                                       const float* __restrict__ sh,
                                                       const float* __restrict__ c2w) {
    __shared__ float skey[NG];
    int tid = threadIdx.x;
    int n = blockIdx.x * 256 + tid;

    // w2c rotation row 2 and translation (depth row): Wm[2][j] = -c2w[j*4+2]
    float W20 = -c2w[2], W21 = -c2w[6], W22 = -c2w[10];
    float tx0 = c2w[3], ty0 = c2w[7], tz0 = c2w[11];
    float tw2 = -(W20 * tx0 + W21 * ty0 + W22 * tz0);

    // every block computes all depth keys (cheap, removes cross-block dependency)
    for (int i = tid; i < NG; i += 256) {
        float mx = means[3 * i + 0], my = means[3 * i + 1], mz = means[3 * i + 2];
        float d = W20 * mx + W21 * my + W22 * mz + tw2;
        bool mk = (d > NEAR_) && (d < FAR_);
        skey[i] = mk ? d : FINF;
    }
    __syncthreads();
    if (n >= NG) return;

    float key = skey[n];
    bool mask = (key != FINF);

    // counting rank with index tie-break: rank = #{j: kj<k || (kj==k && j<n)}
    int rank = 0;
    const float4* sk4 = (const float4*)skey;
#pragma unroll 4
    for (int j4 = 0; j4 < NG / 4; ++j4) {
        float4 v = sk4[j4];
        int jb = j4 * 4;
        rank += (v.x < key) || ((v.x == key) && (jb + 0 < n));
        rank += (v.y < key) || ((v.y == key) && (jb + 1 < n));
        rank += (v.z < key) || ((v.z == key) && (jb + 2 < n));
        rank += (v.w < key) || ((v.w == key) && (jb + 3 < n));
    }

    // ---- full per-gaussian preprocess ----
    const float sgn[3] = {1.f, -1.f, -1.f};
    float Wm[3][3];
#pragma unroll
    for (int i = 0; i < 3; ++i)
#pragma unroll
        for (int j = 0; j < 3; ++j)
            Wm[i][j] = c2w[j * 4 + i] * sgn[i];
    float tw[3];
#pragma unroll
    for (int i = 0; i < 3; ++i)
        tw[i] = -(Wm[i][0] * tx0 + Wm[i][1] * ty0 + Wm[i][2] * tz0);

    float mx = means[3 * n + 0], my = means[3 * n + 1], mz = means[3 * n + 2];
    float mc[3];
#pragma unroll
    for (int i = 0; i < 3; ++i)
        mc[i] = Wm[i][0] * mx + Wm[i][1] * my + Wm[i][2] * mz + tw[i];

    // view direction
    float dx = mx - tx0, dy = my - ty0, dz = mz - tz0;
    float rn = rsqrtf(dx * dx + dy * dy + dz * dz);
    float x = dx * rn, y = dy * rn, z = dz * rn;

    float basis[16];
    basis[0]  = 0.282095f;
    basis[1]  = -0.488603f * y;
    basis[2]  = 0.488603f * z;
    basis[3]  = -0.488603f * x;
    basis[4]  = 1.092548f * x * y;
    basis[5]  = -1.092548f * y * z;
    basis[6]  = 0.315392f * (3.f * z * z - 1.f);
    basis[7]  = -1.092548f * x * z;
    basis[8]  = 0.546274f * (x * x - y * y);
    basis[9]  = -0.590044f * y * (3.f * x * x - y * y);
    basis[10] = 2.890611f * x * y * z;
    basis[11] = -0.457046f * y * (5.f * z * z - 1.f);
    basis[12] = 0.373176f * z * (5.f * z * z - 3.f);
    basis[13] = -0.457046f * x * (5.f * z * z - 1.f);
    basis[14] = 1.445306f * z * (x * x - y * y);
    basis[15] = -0.590044f * x * (x * x - 3.f * y * y);

    float col[3] = {0.f, 0.f, 0.f};
    const float* shn = sh + n * 48;
#pragma unroll
    for (int k = 0; k < 16; ++k) {
        col[0] = fmaf(basis[k], shn[k * 3 + 0], col[0]);
        col[1] = fmaf(basis[k], shn[k * 3 + 1], col[1]);
        col[2] = fmaf(basis[k], shn[k * 3 + 2], col[2]);
    }
#pragma unroll
    for (int c = 0; c < 3; ++c) col[c] = fmaxf(col[c] + 0.5f, 0.f);

    float qw = quats[4 * n + 0], qx = quats[4 * n + 1], qy = quats[4 * n + 2], qz = quats[4 * n + 3];
    float qn = rsqrtf(qw * qw + qx * qx + qy * qy + qz * qz);
    qw *= qn; qx *= qn; qy *= qn; qz *= qn;
    float Rg[3][3];
    Rg[0][0] = 1.f - 2.f * (qy * qy + qz * qz);
    Rg[0][1] = 2.f * (qx * qy - qz * qw);
    Rg[0][2] = 2.f * (qx * qz + qy * qw);
    Rg[1][0] = 2.f * (qx * qy + qz * qw);
    Rg[1][1] = 1.f - 2.f * (qx * qx + qz * qz);
    Rg[1][2] = 2.f * (qy * qz - qx * qw);
    Rg[2][0] = 2.f * (qx * qz - qy * qw);
    Rg[2][1] = 2.f * (qy * qz + qx * qw);
    Rg[2][2] = 1.f - 2.f * (qx * qx + qy * qy);

    float e0 = expf(log_scales[3 * n + 0]);
    float e1 = expf(log_scales[3 * n + 1]);
    float e2 = expf(log_scales[3 * n + 2]);

    float Mc[3][3];
#pragma unroll
    for (int i = 0; i < 3; ++i) {
        float m0 = Wm[i][0] * Rg[0][0] + Wm[i][1] * Rg[1][0] + Wm[i][2] * Rg[2][0];
        float m1 = Wm[i][0] * Rg[0][1] + Wm[i][1] * Rg[1][1] + Wm[i][2] * Rg[2][1];
        float m2 = Wm[i][0] * Rg[0][2] + Wm[i][1] * Rg[1][2] + Wm[i][2] * Rg[2][2];
        Mc[i][0] = m0 * e0; Mc[i][1] = m1 * e1; Mc[i][2] = m2 * e2;
    }

    float tcx = mc[0], tcy = mc[1], tcz = mc[2];
    float rz = 1.f / tcz;
    float j00 = FX_ * rz, j02 = -FX_ * tcx * rz * rz;
    float j11 = FY_ * rz, j12 = -FY_ * tcy * rz * rz;

    float P0[3], P1[3];
#pragma unroll
    for (int j = 0; j < 3; ++j) {
        P0[j] = j00 * Mc[0][j] + j02 * Mc[2][j];
        P1[j] = j11 * Mc[1][j] + j12 * Mc[2][j];
    }
    float a = P0[0] * P0[0] + P0[1] * P0[1] + P0[2] * P0[2] + EPS2D_;
    float cc = P1[0] * P1[0] + P1[1] * P1[1] + P1[2] * P1[2] + EPS2D_;
    float b = P0[0] * P1[0] + P0[1] * P1[1] + P0[2] * P1[2];
    float det = a * cc - b * b;
    float inv = 1.f / det;
    float A = cc * inv, B = -b * inv, C = a * inv;

    float axx = -0.5f * LOG2E_ * A;
    float ayy = -0.5f * LOG2E_ * C;
    float axy = -LOG2E_ * B;

    float u = FX_ * tcx * rz + CX_;
    float v = FY_ * tcy * rz + CY_;

    float opac = 1.f / (1.f + expf(-opacity_logits[n]));
    float lo = log2f(opac);
    if (!mask) lo = -1e30f;

    // bbox of ellipse p = SKIP_THR
    float aq = -axx, bq = -axy, cq = -ayy;
    float t = lo - SKIP_THR;
    float rx = -1.f, ry = -1.f;
    if (t > 0.f) {
        float denom = 4.f * aq * cq - bq * bq;
        float rden = 4.f * t / denom;
        rx = sqrtf(cq * rden) + 1.0f;
        ry = sqrtf(aq * rden) + 1.0f;
    }

    g_s0[rank]   = make_float4(u, v, axx, axy);
    g_s1[rank]   = make_float4(ayy, lo, col[0], col[1]);
    g_scul[rank] = make_float4(u, v, rx, ry);
    g_sbl[rank]  = col[2];
}

// ---------------- kernel 2: culled, segmented per-pixel compositing ----------------
__global__ void __launch_bounds__(32 * NSEG) render_kernel(float* __restrict__ out) {
    int lane = threadIdx.x;              // 0..31  -> pixel within 32-px row strip
    int seg  = threadIdx.y;              // 0..NSEG-1 -> gaussian segment
    int pixbase = blockIdx.x * 32;       // strips never cross rows: 160 = 5*32
    int px0 = pixbase % WID;
    int py  = pixbase / WID;

    float yc = (float)py;
    float xc = (float)px0 + 15.5f;
    float lx = (float)lane - 15.5f;
    float fx0 = (float)px0;
    float fx1 = (float)(px0 + 31);

    __shared__ unsigned short slist[NSEG][SEGLEN];
    __shared__ float          sblue[NSEG][SEGLEN];
    __shared__ float4         sred[NSEG][32];

    // ---- scan & compact this warp's segment (coalesced) ----
    int i0 = seg * SEGLEN;
    int cnt = 0;
#pragma unroll
    for (int r = 0; r < SEGLEN / 32; ++r) {
        int g = i0 + r * 32 + lane;
        float4 cb = g_scul[g];           // u, v, rx, ry
        bool pass = (fabsf(cb.y - yc) < cb.w) &&
                    (cb.x + cb.z > fx0) && (cb.x - cb.z < fx1);
        unsigned m = __ballot_sync(0xffffffffu, pass);
        if (pass) {
            int slot = cnt + __popc(m & ((1u << lane) - 1u));
            slist[seg][slot] = (unsigned short)g;
            sblue[seg][slot] = g_sbl[g];
        }
        cnt += __popc(m);
    }
    __syncwarp();

    // ---- composite survivors (front-to-back within segment) ----
    float T = 1.f, cr = 0.f, cg = 0.f, cbl = 0.f;
    for (int j = 0; j < cnt; ++j) {
        int g = slist[seg][j];
        float4 a  = __ldg(&g_s0[g]);     // u, v, axx, axy  (broadcast)
        float4 b4 = __ldg(&g_s1[g]);     // ayy, lo, r, g
        float du = xc - a.x;             // uniform across warp
        float dv = yc - a.y;
        float tx = a.z * du;
        float s  = fmaf(a.w, dv, tx);
        float k0 = fmaf(du, s, b4.y);
        k0 = fmaf(b4.x * dv, dv, k0);
        float k1 = fmaf(a.w, dv, tx + tx);
        float p  = fmaf(fmaf(a.z, lx, k1), lx, k0);
        if (p > SKIP_THR) {
            float alpha = fminf(fast_exp2(p), 0.999f);
            float w = T * alpha;
            cr  = fmaf(w, b4.z, cr);
            cg  = fmaf(w, b4.w, cg);
            cbl = fmaf(w, sblue[seg][j], cbl);
            T   = fmaf(-T, alpha, T);
        }
    }

    sred[seg][lane] = make_float4(T, cr, cg, cbl);
    __syncthreads();

    if (seg == 0) {
        float Tp = 1.f, R = 0.f, G = 0.f, B = 0.f;
#pragma unroll
        for (int k = 0; k < NSEG; ++k) {
            float4 vv = sred[k][lane];
            R = fmaf(Tp, vv.y, R);
            G = fmaf(Tp, vv.z, G);
            B = fmaf(Tp, vv.w, B);
            Tp *= vv.x;
        }
        int pix = pixbase + lane;
        out[pix * 3 + 0] = R;
        out[pix * 3 + 1] = G;
        out[pix * 3 + 2] = B;
    }
}

// ---------------- launch ----------------
extern "C" void kernel_launch(void* const* d_in, const int* in_sizes, int n_in,
                              void* d_out, int out_size) {
    const float* means   = (const float*)d_in[0];
    const float* quats   = (const float*)d_in[1];
    const float* lscales = (const float*)d_in[2];
    const float* opl     = (const float*)d_in[3];
    const float* sh      = (const float*)d_in[4];
    const float* c2w     = (const float*)d_in[5];
    float* out = (float*)d_out;

    pre_rank_kernel<<<(NG + 255) / 256, 256>>>(means, quats, lscales, opl, sh, c2w);
    render_kernel<<<(WID * HEI) / 32, dim3(32, NSEG)>>>(out);
}

// round 4
// speedup vs baseline: 2.2808x; 1.3255x over previous
#include <cuda_runtime.h>
#include <math.h>

#define NG        1536
#define WID       160
#define HEI       128
#define FX_       146.44f
#define FY_       146.44f
#define CX_       80.0f
#define CY_       64.0f
#define EPS2D_    0.3f
#define NEAR_     0.01f
#define FAR_      1e10f
#define NSEG      16
#define SEGLEN    (NG / NSEG)          // 96
#define LOG2E_    1.4426950408889634f
#define SKIP_THR  (-20.0f)             // log2 units; culled alpha <= ~1e-6
#define FINF      __int_as_float(0x7f800000)

// ---------------- device scratch (sorted-by-depth gaussian data) ----------------
__device__ float4 g_s0[NG];            // u, v, axx, axy   (log2-space conic, opacity folded)
__device__ float4 g_s1[NG];            // ayy, lo, r, g
__device__ float4 g_scul[NG];          // u, v, rx, ry     (cull bbox)
__device__ float  g_sbl[NG];           // blue

__device__ __forceinline__ float fast_exp2(float x) {
    float r;
    asm("ex2.approx.f32 %0, %1;" : "=f"(r) : "f"(x));
    return r;
}

// ---------------- kernel 1: preprocess + counting-rank scatter ----------------
// 48 blocks x 32 threads: one warp per SM, maximal SM spread for the serial
// rank scan and the long-dependency preprocess chain.
__global__ void __launch_bounds__(32) pre_rank_kernel(const float* __restrict__ means,
                                                      const float* __restrict__ quats,
                                                      const float* __restrict__ log_scales,
                                                      const float* __restrict__ opacity_logits,
                                                      const float* __restrict__ sh,
                                                      const float* __restrict__ c2w) {
    __shared__ float skey[NG];
    int tid = threadIdx.x;                 // 0..31
    int n = blockIdx.x * 32 + tid;         // 48*32 = 1536 exactly

    // w2c depth row: Wm[2][j] = -c2w[j*4+2]
    float W20 = -c2w[2], W21 = -c2w[6], W22 = -c2w[10];
    float tx0 = c2w[3], ty0 = c2w[7], tz0 = c2w[11];
    float tw2 = -(W20 * tx0 + W21 * ty0 + W22 * tz0);

    // every block computes all depth keys (cheap; removes cross-block dependency)
    for (int i = tid; i < NG; i += 32) {
        float mx = means[3 * i + 0], my = means[3 * i + 1], mz = means[3 * i + 2];
        float d = W20 * mx + W21 * my + W22 * mz + tw2;
        bool mk = (d > NEAR_) && (d < FAR_);
        skey[i] = mk ? d : FINF;
    }
    __syncthreads();

    float key = skey[n];
    bool mask = (key != FINF);

    // counting rank with index tie-break: rank = #{j: kj<k || (kj==k && j<n)}
    int rank = 0;
    const float4* sk4 = (const float4*)skey;
#pragma unroll 4
    for (int j4 = 0; j4 < NG / 4; ++j4) {
        float4 v = sk4[j4];
        int jb = j4 * 4;
        rank += (v.x < key) || ((v.x == key) && (jb + 0 < n));
        rank += (v.y < key) || ((v.y == key) && (jb + 1 < n));
        rank += (v.z < key) || ((v.z == key) && (jb + 2 < n));
        rank += (v.w < key) || ((v.w == key) && (jb + 3 < n));
    }

    // ---- full per-gaussian preprocess ----
    const float sgn[3] = {1.f, -1.f, -1.f};
    float Wm[3][3];
#pragma unroll
    for (int i = 0; i < 3; ++i)
#pragma unroll
        for (int j = 0; j < 3; ++j)
            Wm[i][j] = c2w[j * 4 + i] * sgn[i];
    float tw[3];
#pragma unroll
    for (int i = 0; i < 3; ++i)
        tw[i] = -(Wm[i][0] * tx0 + Wm[i][1] * ty0 + Wm[i][2] * tz0);

    float mx = means[3 * n + 0], my = means[3 * n + 1], mz = means[3 * n + 2];
    float mc[3];
#pragma unroll
    for (int i = 0; i < 3; ++i)
        mc[i] = Wm[i][0] * mx + Wm[i][1] * my + Wm[i][2] * mz + tw[i];

    // view direction
    float dx = mx - tx0, dy = my - ty0, dz = mz - tz0;
    float rn = rsqrtf(dx * dx + dy * dy + dz * dz);
    float x = dx * rn, y = dy * rn, z = dz * rn;

    float basis[16];
    basis[0]  = 0.282095f;
    basis[1]  = -0.488603f * y;
    basis[2]  = 0.488603f * z;
    basis[3]  = -0.488603f * x;
    basis[4]  = 1.092548f * x * y;
    basis[5]  = -1.092548f * y * z;
    basis[6]  = 0.315392f * (3.f * z * z - 1.f);
    basis[7]  = -1.092548f * x * z;
    basis[8]  = 0.546274f * (x * x - y * y);
    basis[9]  = -0.590044f * y * (3.f * x * x - y * y);
    basis[10] = 2.890611f * x * y * z;
    basis[11] = -0.457046f * y * (5.f * z * z - 1.f);
    basis[12] = 0.373176f * z * (5.f * z * z - 3.f);
    basis[13] = -0.457046f * x * (5.f * z * z - 1.f);
    basis[14] = 1.445306f * z * (x * x - y * y);
    basis[15] = -0.590044f * x * (x * x - 3.f * y * y);

    float col[3] = {0.f, 0.f, 0.f};
    const float* shn = sh + n * 48;
#pragma unroll
    for (int k = 0; k < 16; ++k) {
        col[0] = fmaf(basis[k], shn[k * 3 + 0], col[0]);
        col[1] = fmaf(basis[k], shn[k * 3 + 1], col[1]);
        col[2] = fmaf(basis[k], shn[k * 3 + 2], col[2]);
    }
#pragma unroll
    for (int c = 0; c < 3; ++c) col[c] = fmaxf(col[c] + 0.5f, 0.f);

    float qw = quats[4 * n + 0], qx = quats[4 * n + 1], qy = quats[4 * n + 2], qz = quats[4 * n + 3];
    float qn = rsqrtf(qw * qw + qx * qx + qy * qy + qz * qz);
    qw *= qn; qx *= qn; qy *= qn; qz *= qn;
    float Rg[3][3];
    Rg[0][0] = 1.f - 2.f * (qy * qy + qz * qz);
    Rg[0][1] = 2.f * (qx * qy - qz * qw);
    Rg[0][2] = 2.f * (qx * qz + qy * qw);
    Rg[1][0] = 2.f * (qx * qy + qz * qw);
    Rg[1][1] = 1.f - 2.f * (qx * qx + qz * qz);
    Rg[1][2] = 2.f * (qy * qz - qx * qw);
    Rg[2][0] = 2.f * (qx * qz - qy * qw);
    Rg[2][1] = 2.f * (qy * qz + qx * qw);
    Rg[2][2] = 1.f - 2.f * (qx * qx + qy * qy);

    float e0 = expf(log_scales[3 * n + 0]);
    float e1 = expf(log_scales[3 * n + 1]);
    float e2 = expf(log_scales[3 * n + 2]);

    float Mc[3][3];
#pragma unroll
    for (int i = 0; i < 3; ++i) {
        float m0 = Wm[i][0] * Rg[0][0] + Wm[i][1] * Rg[1][0] + Wm[i][2] * Rg[2][0];
        float m1 = Wm[i][0] * Rg[0][1] + Wm[i][1] * Rg[1][1] + Wm[i][2] * Rg[2][1];
        float m2 = Wm[i][0] * Rg[0][2] + Wm[i][1] * Rg[1][2] + Wm[i][2] * Rg[2][2];
        Mc[i][0] = m0 * e0; Mc[i][1] = m1 * e1; Mc[i][2] = m2 * e2;
    }

    float tcx = mc[0], tcy = mc[1], tcz = mc[2];
    float rz = 1.f / tcz;
    float j00 = FX_ * rz, j02 = -FX_ * tcx * rz * rz;
    float j11 = FY_ * rz, j12 = -FY_ * tcy * rz * rz;

    float P0[3], P1[3];
#pragma unroll
    for (int j = 0; j < 3; ++j) {
        P0[j] = j00 * Mc[0][j] + j02 * Mc[2][j];
        P1[j] = j11 * Mc[1][j] + j12 * Mc[2][j];
    }
    float a = P0[0] * P0[0] + P0[1] * P0[1] + P0[2] * P0[2] + EPS2D_;
    float cc = P1[0] * P1[0] + P1[1] * P1[1] + P1[2] * P1[2] + EPS2D_;
    float b = P0[0] * P1[0] + P0[1] * P1[1] + P0[2] * P1[2];
    float det = a * cc - b * b;
    float inv = 1.f / det;
    float A = cc * inv, B = -b * inv, C = a * inv;

    float axx = -0.5f * LOG2E_ * A;
    float ayy = -0.5f * LOG2E_ * C;
    float axy = -LOG2E_ * B;

    float u = FX_ * tcx * rz + CX_;
    float v = FY_ * tcy * rz + CY_;

    float opac = 1.f / (1.f + expf(-opacity_logits[n]));
    float lo = log2f(opac);
    if (!mask) lo = -1e30f;

    // bbox of ellipse p = SKIP_THR
    float aq = -axx, bq = -axy, cq = -ayy;
    float t = lo - SKIP_THR;
    float rx = -1.f, ry = -1.f;
    if (t > 0.f) {
        float denom = 4.f * aq * cq - bq * bq;
        float rden = 4.f * t / denom;
        rx = sqrtf(cq * rden) + 1.0f;
        ry = sqrtf(aq * rden) + 1.0f;
    }

    g_s0[rank]   = make_float4(u, v, axx, axy);
    g_s1[rank]   = make_float4(ayy, lo, col[0], col[1]);
    g_scul[rank] = make_float4(u, v, rx, ry);
    g_sbl[rank]  = col[2];
}

// ---------------- kernel 2: culled, segmented per-pixel compositing ----------------
__global__ void __launch_bounds__(32 * NSEG) render_kernel(float* __restrict__ out) {
    int lane = threadIdx.x;              // 0..31  -> pixel within 32-px row strip
    int seg  = threadIdx.y;              // 0..NSEG-1 -> gaussian segment
    int pixbase = blockIdx.x * 32;       // strips never cross rows: 160 = 5*32
    int px0 = pixbase % WID;
    int py  = pixbase / WID;

    float yc = (float)py;
    float xc = (float)px0 + 15.5f;
    float lx = (float)lane - 15.5f;
    float fx0 = (float)px0;
    float fx1 = (float)(px0 + 31);

    __shared__ unsigned short slist[NSEG][SEGLEN];
    __shared__ float          sblue[NSEG][SEGLEN];
    __shared__ float4         sred[NSEG][32];

    // ---- scan & compact this warp's segment (coalesced) ----
    int i0 = seg * SEGLEN;
    int cnt = 0;
#pragma unroll
    for (int r = 0; r < SEGLEN / 32; ++r) {
        int g = i0 + r * 32 + lane;
        float4 cb = g_scul[g];           // u, v, rx, ry
        bool pass = (fabsf(cb.y - yc) < cb.w) &&
                    (cb.x + cb.z > fx0) && (cb.x - cb.z < fx1);
        unsigned m = __ballot_sync(0xffffffffu, pass);
        if (pass) {
            int slot = cnt + __popc(m & ((1u << lane) - 1u));
            slist[seg][slot] = (unsigned short)g;
            sblue[seg][slot] = g_sbl[g];
        }
        cnt += __popc(m);
    }
    __syncwarp();

    // ---- composite survivors (front-to-back within segment) ----
    float T = 1.f, cr = 0.f, cg = 0.f, cbl = 0.f;
    for (int j = 0; j < cnt; ++j) {
        int g = slist[seg][j];
        float4 a  = __ldg(&g_s0[g]);     // u, v, axx, axy  (broadcast)
        float4 b4 = __ldg(&g_s1[g]);     // ayy, lo, r, g
        float du = xc - a.x;             // uniform across warp
        float dv = yc - a.y;
        float tx = a.z * du;
        float s  = fmaf(a.w, dv, tx);
        float k0 = fmaf(du, s, b4.y);
        k0 = fmaf(b4.x * dv, dv, k0);
        float k1 = fmaf(a.w, dv, tx + tx);
        float p  = fmaf(fmaf(a.z, lx, k1), lx, k0);
        if (p > SKIP_THR) {
            float alpha = fminf(fast_exp2(p), 0.999f);
            float w = T * alpha;
            cr  = fmaf(w, b4.z, cr);
            cg  = fmaf(w, b4.w, cg);
            cbl = fmaf(w, sblue[seg][j], cbl);
            T   = fmaf(-T, alpha, T);
        }
    }

    sred[seg][lane] = make_float4(T, cr, cg, cbl);
    __syncthreads();

    if (seg == 0) {
        float Tp = 1.f, R = 0.f, G = 0.f, B = 0.f;
#pragma unroll
        for (int k = 0; k < NSEG; ++k) {
            float4 vv = sred[k][lane];
            R = fmaf(Tp, vv.y, R);
            G = fmaf(Tp, vv.z, G);
            B = fmaf(Tp, vv.w, B);
            Tp *= vv.x;
        }
        int pix = pixbase + lane;
        out[pix * 3 + 0] = R;
        out[pix * 3 + 1] = G;
        out[pix * 3 + 2] = B;
    }
}

// ---------------- launch ----------------
extern "C" void kernel_launch(void* const* d_in, const int* in_sizes, int n_in,
                              void* d_out, int out_size) {
    const float* means   = (const float*)d_in[0];
    const float* quats   = (const float*)d_in[1];
    const float* lscales = (const float*)d_in[2];
    const float* opl     = (const float*)d_in[3];
    const float* sh      = (const float*)d_in[4];
    const float* c2w     = (const float*)d_in[5];
    float* out = (float*)d_out;

    pre_rank_kernel<<<48, 32>>>(means, quats, lscales, opl, sh, c2w);
    render_kernel<<<(WID * HEI) / 32, dim3(32, NSEG)>>>(out);
}

// round 5
// speedup vs baseline: 3.3765x; 1.4804x over previous
#include <cuda_runtime.h>
#include <math.h>

#define NG        1536
#define WID       160
#define HEI       128
#define FX_       146.44f
#define FY_       146.44f
#define CX_       80.0f
#define CY_       64.0f
#define EPS2D_    0.3f
#define NEAR_     0.01f
#define FAR_      1e10f
#define NSEG      16
#define SEGLEN    (NG / NSEG)          // 96
#define LOG2E_    1.4426950408889634f
#define SKIP_THR  (-20.0f)             // log2 units; culled alpha <= ~1e-6
#define FINF      __int_as_float(0x7f800000)
#define NPART     4                    // rank-scan split factor
#define CHUNK     (NG / NPART)         // 384 keys per scanning thread

// ---------------- device scratch (sorted-by-depth gaussian data) ----------------
__device__ float4 g_s0[NG];            // u, v, axx, axy   (log2-space conic, opacity folded)
__device__ float4 g_s1[NG];            // ayy, lo, r, g
__device__ float4 g_scul[NG];          // u, v, rx, ry     (cull bbox)
__device__ float  g_sbl[NG];           // blue

__device__ __forceinline__ float fast_exp2(float x) {
    float r;
    asm("ex2.approx.f32 %0, %1;" : "=f"(r) : "f"(x));
    return r;
}

// ---------------- kernel 1: preprocess (warp 0) || split rank scan (warps 1-4) ----------------
// 48 blocks x 160 threads. Each block owns 32 gaussians.
__global__ void __launch_bounds__(160) pre_rank_kernel(const float* __restrict__ means,
                                                       const float* __restrict__ quats,
                                                       const float* __restrict__ log_scales,
                                                       const float* __restrict__ opacity_logits,
                                                       const float* __restrict__ sh,
                                                       const float* __restrict__ c2w) {
    __shared__ float skey[NG];
    __shared__ int   srank[NPART][32];

    int tid  = threadIdx.x;
    int warp = tid >> 5;               // 0..4
    int lane = tid & 31;

    // w2c depth row: Wm[2][j] = -c2w[j*4+2]
    float W20 = -c2w[2], W21 = -c2w[6], W22 = -c2w[10];
    float tx0 = c2w[3], ty0 = c2w[7], tz0 = c2w[11];
    float tw2 = -(W20 * tx0 + W21 * ty0 + W22 * tz0);

    // all 160 threads cooperatively compute all depth keys
    for (int i = tid; i < NG; i += 160) {
        float mx = means[3 * i + 0], my = means[3 * i + 1], mz = means[3 * i + 2];
        float d = W20 * mx + W21 * my + W22 * mz + tw2;
        bool mk = (d > NEAR_) && (d < FAR_);
        skey[i] = mk ? d : FINF;
    }
    __syncthreads();

    int n = blockIdx.x * 32 + lane;    // gaussian owned by this lane

    if (warp >= 1) {
        // ---- split rank scan: warp w scans chunk (w-1) for gaussian n ----
        int part = warp - 1;
        float key = skey[n];
        const float4* sk4 = (const float4*)(skey + part * CHUNK);
        int jb0 = part * CHUNK;
        int r0 = 0, r1 = 0, r2 = 0, r3 = 0;
#pragma unroll 4
        for (int j4 = 0; j4 < CHUNK / 4; ++j4) {
            float4 v = sk4[j4];
            int jb = jb0 + j4 * 4;
            r0 += (v.x < key) || ((v.x == key) && (jb + 0 < n));
            r1 += (v.y < key) || ((v.y == key) && (jb + 1 < n));
            r2 += (v.z < key) || ((v.z == key) && (jb + 2 < n));
            r3 += (v.w < key) || ((v.w == key) && (jb + 3 < n));
        }
        srank[part][lane] = (r0 + r1) + (r2 + r3);
        __syncthreads();
        return;                        // scanning warps done (second sync below matches)
    }

    // ================= warp 0: full preprocess for gaussian n =================
    const float sgn[3] = {1.f, -1.f, -1.f};
    float Wm[3][3];
#pragma unroll
    for (int i = 0; i < 3; ++i)
#pragma unroll
        for (int j = 0; j < 3; ++j)
            Wm[i][j] = c2w[j * 4 + i] * sgn[i];
    float tw[3];
#pragma unroll
    for (int i = 0; i < 3; ++i)
        tw[i] = -(Wm[i][0] * tx0 + Wm[i][1] * ty0 + Wm[i][2] * tz0);

    float mx = means[3 * n + 0], my = means[3 * n + 1], mz = means[3 * n + 2];
    float mc[3];
#pragma unroll
    for (int i = 0; i < 3; ++i)
        mc[i] = Wm[i][0] * mx + Wm[i][1] * my + Wm[i][2] * mz + tw[i];
    float depth = mc[2];
    bool mask = (depth > NEAR_) && (depth < FAR_);

    // view direction
    float dx = mx - tx0, dy = my - ty0, dz = mz - tz0;
    float rn = rsqrtf(dx * dx + dy * dy + dz * dz);
    float x = dx * rn, y = dy * rn, z = dz * rn;

    float basis[16];
    basis[0]  = 0.282095f;
    basis[1]  = -0.488603f * y;
    basis[2]  = 0.488603f * z;
    basis[3]  = -0.488603f * x;
    basis[4]  = 1.092548f * x * y;
    basis[5]  = -1.092548f * y * z;
    basis[6]  = 0.315392f * (3.f * z * z - 1.f);
    basis[7]  = -1.092548f * x * z;
    basis[8]  = 0.546274f * (x * x - y * y);
    basis[9]  = -0.590044f * y * (3.f * x * x - y * y);
    basis[10] = 2.890611f * x * y * z;
    basis[11] = -0.457046f * y * (5.f * z * z - 1.f);
    basis[12] = 0.373176f * z * (5.f * z * z - 3.f);
    basis[13] = -0.457046f * x * (5.f * z * z - 1.f);
    basis[14] = 1.445306f * z * (x * x - y * y);
    basis[15] = -0.590044f * x * (x * x - 3.f * y * y);

    float col[3] = {0.f, 0.f, 0.f};
    const float* shn = sh + n * 48;
#pragma unroll
    for (int k = 0; k < 16; ++k) {
        col[0] = fmaf(basis[k], shn[k * 3 + 0], col[0]);
        col[1] = fmaf(basis[k], shn[k * 3 + 1], col[1]);
        col[2] = fmaf(basis[k], shn[k * 3 + 2], col[2]);
    }
#pragma unroll
    for (int c = 0; c < 3; ++c) col[c] = fmaxf(col[c] + 0.5f, 0.f);

    float qw = quats[4 * n + 0], qx = quats[4 * n + 1], qy = quats[4 * n + 2], qz = quats[4 * n + 3];
    float qn = rsqrtf(qw * qw + qx * qx + qy * qy + qz * qz);
    qw *= qn; qx *= qn; qy *= qn; qz *= qn;
    float Rg[3][3];
    Rg[0][0] = 1.f - 2.f * (qy * qy + qz * qz);
    Rg[0][1] = 2.f * (qx * qy - qz * qw);
    Rg[0][2] = 2.f * (qx * qz + qy * qw);
    Rg[1][0] = 2.f * (qx * qy + qz * qw);
    Rg[1][1] = 1.f - 2.f * (qx * qx + qz * qz);
    Rg[1][2] = 2.f * (qy * qz - qx * qw);
    Rg[2][0] = 2.f * (qx * qz - qy * qw);
    Rg[2][1] = 2.f * (qy * qz + qx * qw);
    Rg[2][2] = 1.f - 2.f * (qx * qx + qy * qy);

    float e0 = expf(log_scales[3 * n + 0]);
    float e1 = expf(log_scales[3 * n + 1]);
    float e2 = expf(log_scales[3 * n + 2]);

    float Mc[3][3];
#pragma unroll
    for (int i = 0; i < 3; ++i) {
        float m0 = Wm[i][0] * Rg[0][0] + Wm[i][1] * Rg[1][0] + Wm[i][2] * Rg[2][0];
        float m1 = Wm[i][0] * Rg[0][1] + Wm[i][1] * Rg[1][1] + Wm[i][2] * Rg[2][1];
        float m2 = Wm[i][0] * Rg[0][2] + Wm[i][1] * Rg[1][2] + Wm[i][2] * Rg[2][2];
        Mc[i][0] = m0 * e0; Mc[i][1] = m1 * e1; Mc[i][2] = m2 * e2;
    }

    float tcx = mc[0], tcy = mc[1], tcz = mc[2];
    float rz = 1.f / tcz;
    float j00 = FX_ * rz, j02 = -FX_ * tcx * rz * rz;
    float j11 = FY_ * rz, j12 = -FY_ * tcy * rz * rz;

    float P0[3], P1[3];
#pragma unroll
    for (int j = 0; j < 3; ++j) {
        P0[j] = j00 * Mc[0][j] + j02 * Mc[2][j];
        P1[j] = j11 * Mc[1][j] + j12 * Mc[2][j];
    }
    float a = P0[0] * P0[0] + P0[1] * P0[1] + P0[2] * P0[2] + EPS2D_;
    float cc = P1[0] * P1[0] + P1[1] * P1[1] + P1[2] * P1[2] + EPS2D_;
    float b = P0[0] * P1[0] + P0[1] * P1[1] + P0[2] * P1[2];
    float det = a * cc - b * b;
    float inv = 1.f / det;
    float A = cc * inv, B = -b * inv, C = a * inv;

    float axx = -0.5f * LOG2E_ * A;
    float ayy = -0.5f * LOG2E_ * C;
    float axy = -LOG2E_ * B;

    float u = FX_ * tcx * rz + CX_;
    float v = FY_ * tcy * rz + CY_;

    float opac = 1.f / (1.f + expf(-opacity_logits[n]));
    float lo = log2f(opac);
    if (!mask) lo = -1e30f;

    // bbox of ellipse p = SKIP_THR
    float aq = -axx, bq = -axy, cq = -ayy;
    float t = lo - SKIP_THR;
    float rx = -1.f, ry = -1.f;
    if (t > 0.f) {
        float denom = 4.f * aq * cq - bq * bq;
        float rden = 4.f * t / denom;
        rx = sqrtf(cq * rden) + 1.0f;
        ry = sqrtf(aq * rden) + 1.0f;
    }

    __syncthreads();   // wait for scanning warps' partial ranks

    int rank = (srank[0][lane] + srank[1][lane]) + (srank[2][lane] + srank[3][lane]);

    g_s0[rank]   = make_float4(u, v, axx, axy);
    g_s1[rank]   = make_float4(ayy, lo, col[0], col[1]);
    g_scul[rank] = make_float4(u, v, rx, ry);
    g_sbl[rank]  = col[2];
}

// ---------------- kernel 2: culled, segmented per-pixel compositing ----------------
__global__ void __launch_bounds__(32 * NSEG) render_kernel(float* __restrict__ out) {
    int lane = threadIdx.x;              // 0..31  -> pixel within 32-px row strip
    int seg  = threadIdx.y;              // 0..NSEG-1 -> gaussian segment
    int pixbase = blockIdx.x * 32;       // strips never cross rows: 160 = 5*32
    int px0 = pixbase % WID;
    int py  = pixbase / WID;

    float yc = (float)py;
    float xc = (float)px0 + 15.5f;
    float lx = (float)lane - 15.5f;
    float fx0 = (float)px0;
    float fx1 = (float)(px0 + 31);

    __shared__ unsigned short slist[NSEG][SEGLEN];
    __shared__ float          sblue[NSEG][SEGLEN];
    __shared__ float4         sred[NSEG][32];

    // ---- scan & compact this warp's segment (coalesced) ----
    int i0 = seg * SEGLEN;
    int cnt = 0;
#pragma unroll
    for (int r = 0; r < SEGLEN / 32; ++r) {
        int g = i0 + r * 32 + lane;
        float4 cb = g_scul[g];           // u, v, rx, ry
        bool pass = (fabsf(cb.y - yc) < cb.w) &&
                    (cb.x + cb.z > fx0) && (cb.x - cb.z < fx1);
        unsigned m = __ballot_sync(0xffffffffu, pass);
        if (pass) {
            int slot = cnt + __popc(m & ((1u << lane) - 1u));
            slist[seg][slot] = (unsigned short)g;
            sblue[seg][slot] = g_sbl[g];
        }
        cnt += __popc(m);
    }
    __syncwarp();

    // ---- composite survivors (front-to-back within segment) ----
    float T = 1.f, cr = 0.f, cg = 0.f, cbl = 0.f;
    for (int j = 0; j < cnt; ++j) {
        int g = slist[seg][j];
        float4 a  = __ldg(&g_s0[g]);     // u, v, axx, axy  (broadcast)
        float4 b4 = __ldg(&g_s1[g]);     // ayy, lo, r, g
        float du = xc - a.x;             // uniform across warp
        float dv = yc - a.y;
        float tx = a.z * du;
        float s  = fmaf(a.w, dv, tx);
        float k0 = fmaf(du, s, b4.y);
        k0 = fmaf(b4.x * dv, dv, k0);
        float k1 = fmaf(a.w, dv, tx + tx);
        float p  = fmaf(fmaf(a.z, lx, k1), lx, k0);
        if (p > SKIP_THR) {
            float alpha = fminf(fast_exp2(p), 0.999f);
            float w = T * alpha;
            cr  = fmaf(w, b4.z, cr);
            cg  = fmaf(w, b4.w, cg);
            cbl = fmaf(w, sblue[seg][j], cbl);
            T   = fmaf(-T, alpha, T);
        }
    }

    sred[seg][lane] = make_float4(T, cr, cg, cbl);
    __syncthreads();

    if (seg == 0) {
        float Tp = 1.f, R = 0.f, G = 0.f, B = 0.f;
#pragma unroll
        for (int k = 0; k < NSEG; ++k) {
            float4 vv = sred[k][lane];
            R = fmaf(Tp, vv.y, R);
            G = fmaf(Tp, vv.z, G);
            B = fmaf(Tp, vv.w, B);
            Tp *= vv.x;
        }
        int pix = pixbase + lane;
        out[pix * 3 + 0] = R;
        out[pix * 3 + 1] = G;
        out[pix * 3 + 2] = B;
    }
}

// ---------------- launch ----------------
extern "C" void kernel_launch(void* const* d_in, const int* in_sizes, int n_in,
                              void* d_out, int out_size) {
    const float* means   = (const float*)d_in[0];
    const float* quats   = (const float*)d_in[1];
    const float* lscales = (const float*)d_in[2];
    const float* opl     = (const float*)d_in[3];
    const float* sh      = (const float*)d_in[4];
    const float* c2w     = (const float*)d_in[5];
    float* out = (float*)d_out;

    pre_rank_kernel<<<48, 160>>>(means, quats, lscales, opl, sh, c2w);
    render_kernel<<<(WID * HEI) / 32, dim3(32, NSEG)>>>(out);
}